// round 14
// baseline (speedup 1.0000x reference)
#include <cuda_runtime.h>
#include <cuda_bf16.h>
#include <cstdint>

// Problem constants
#define BB 32
#define NN 1024
#define VV 512
#define DD 1536

typedef __nv_bfloat16 bf16;

// Scratch buffers (allocation-free rule: __device__ globals). Big tensors bf16.
__device__ bf16  g_Rb[(size_t)4*DD*DD];   // bf16 copy of R (all layers)
__device__ bf16  g_S [(size_t)BB*NN*NN];
__device__ bf16  g_P [(size_t)BB*NN*NN];
__device__ bf16  g_T [(size_t)BB*NN*NN];
__device__ bf16  g_A [(size_t)BB*NN*NN];
__device__ bf16  g_PN[(size_t)BB*NN*NN];
__device__ float g_qp[(size_t)BB*32*DD];
__device__ float g_u [BB*NN];
__device__ float g_r4[BB*NN];
__device__ float g_w [BB*NN];
__device__ float g_sr[BB*NN];
__device__ float g_a [BB*NN];
__device__ float g_bv[BB*NN];
__device__ float g_p [BB*NN];
__device__ float g_c [BB*VV];

__device__ __forceinline__ float2 bf2f(uint32_t u) {
    return __bfloat1622float2(*(__nv_bfloat162*)&u);
}

// Block-wide reductions over 8 warps (256 threads), value broadcast to all.
__device__ __forceinline__ float blk_max(float v, float* rs, int t) {
    #pragma unroll
    for (int o = 16; o; o >>= 1) v = fmaxf(v, __shfl_xor_sync(0xffffffffu, v, o));
    if ((t & 31) == 0) rs[t >> 5] = v;
    __syncthreads();
    float r = rs[0];
    #pragma unroll
    for (int w = 1; w < 8; w++) r = fmaxf(r, rs[w]);
    return r;
}
__device__ __forceinline__ float blk_sum(float v, float* rs, int t) {
    #pragma unroll
    for (int o = 16; o; o >>= 1) v += __shfl_xor_sync(0xffffffffu, v, o);
    if ((t & 31) == 0) rs[t >> 5] = v;
    __syncthreads();
    float r = rs[0];
    #pragma unroll
    for (int w = 1; w < 8; w++) r += rs[w];
    return r;
}

__device__ __forceinline__ void conv_chunk(const float* __restrict__ src,
                                           bf16* __restrict__ dst, size_t i) {
    float4 v = *(const float4*)(src + i);
    __nv_bfloat162 o0 = __floats2bfloat162_rn(v.x, v.y);
    __nv_bfloat162 o1 = __floats2bfloat162_rn(v.z, v.w);
    uint2 out; out.x = *(uint32_t*)&o0; out.y = *(uint32_t*)&o1;
    *(uint2*)(dst + i) = out;
}

// ---------------------------------------------------------------------------
// R layer-0 -> bf16 (small; runs before gsm1_conv)
// ---------------------------------------------------------------------------
__global__ void r_conv0(const float* __restrict__ R, bf16* __restrict__ Rb) {
    conv_chunk(R, Rb, ((size_t)blockIdx.x * 256 + threadIdx.x) * 4);
}

// ---------------------------------------------------------------------------
// Fused layer 1 (4 rows/block) + R layers 1-3 conversion merged in.
// Zero-writes trimmed to the diagonal 128-tile (upper tiles never read).
// ---------------------------------------------------------------------------
__global__ void __launch_bounds__(256)
gsm1_conv(const float* __restrict__ R, bf16* __restrict__ Rb,
          const int* __restrict__ tok, bf16* __restrict__ P) {
    int t = threadIdx.x;
    if (blockIdx.y >= 32) {                    // convert R layers 1..3
        size_t cidx = ((size_t)(blockIdx.y - 32) * 256 + blockIdx.x);
        size_t i = (size_t)DD*DD + cidx*1024 + t*4;
        conv_chunk(R, Rb, i);
        return;
    }
    int b = blockIdx.y;
    __shared__ float Wsh[DD];
    __shared__ int   tsh[NN];
    __shared__ float rs[8];
    const int* tb = tok + b*NN;
    for (int i = t; i < NN; i += 256) tsh[i] = tb[i];
    int i0 = t*4;
    #pragma unroll
    for (int r = 0; r < 4; r++) {
        int m = blockIdx.x*4 + r;
        __syncthreads();
        int tm = tb[m];
        const bf16* r0 = Rb + (size_t)tm*DD;
        const bf16* r1 = Rb + (size_t)(VV + m)*DD;
        for (int d4 = t*4; d4 < DD; d4 += 1024) {
            uint2 u0 = *(const uint2*)(r0 + d4);
            uint2 u1 = *(const uint2*)(r1 + d4);
            float2 a0 = bf2f(u0.x), a1 = bf2f(u0.y);
            float2 b0 = bf2f(u1.x), b1 = bf2f(u1.y);
            *(float4*)&Wsh[d4] = make_float4(a0.x+b0.x, a0.y+b0.y, a1.x+b1.x, a1.y+b1.y);
        }
        __syncthreads();
        float v[4];
        #pragma unroll
        for (int k = 0; k < 4; k++)
            v[k] = (i0+k <= m) ? (Wsh[tsh[i0+k]] + Wsh[VV + i0+k]) : -1e30f;
        float mx = blk_max(fmaxf(fmaxf(v[0], v[1]), fmaxf(v[2], v[3])), rs, t);
        __syncthreads();
        float e[4];
        #pragma unroll
        for (int k = 0; k < 4; k++)
            e[k] = (i0+k <= m) ? __expf(v[k] - mx) : 0.f;
        float sum = blk_sum(e[0]+e[1]+e[2]+e[3], rs, t);
        float inv = 1.f / sum;
        int kmax = ((m >> 7) + 1) << 7;
        if (i0 < kmax) {
            __nv_bfloat162 o0 = __floats2bfloat162_rn(e[0]*inv, e[1]*inv);
            __nv_bfloat162 o1 = __floats2bfloat162_rn(e[2]*inv, e[3]*inv);
            uint2 out; out.x = *(uint32_t*)&o0; out.y = *(uint32_t*)&o1;
            *(uint2*)(P + ((size_t)b*NN + m)*NN + i0) = out;
        }
    }
}

// ---------------------------------------------------------------------------
// S_k gather: 4 rows per block, 8B vector loads/stores.
// ---------------------------------------------------------------------------
__global__ void __launch_bounds__(256)
gather_S(const bf16* __restrict__ Rb, const int* __restrict__ tok,
         bf16* __restrict__ S) {
    int b = blockIdx.y;
    __shared__ float Wsh[DD];
    __shared__ int   tsh[NN];
    const int* tb = tok + b*NN;
    int t = threadIdx.x;
    for (int i = t; i < NN; i += 256) tsh[i] = tb[i];
    int i0 = t*4;
    #pragma unroll
    for (int r = 0; r < 4; r++) {
        int m = blockIdx.x*4 + r;
        __syncthreads();
        int tm = tb[m];
        const bf16* r0 = Rb + (size_t)tm*DD;
        const bf16* r1 = Rb + (size_t)(VV + m)*DD;
        for (int d4 = t*4; d4 < DD; d4 += 1024) {
            uint2 u0 = *(const uint2*)(r0 + d4);
            uint2 u1 = *(const uint2*)(r1 + d4);
            float2 a0 = bf2f(u0.x), a1 = bf2f(u0.y);
            float2 b0 = bf2f(u1.x), b1 = bf2f(u1.y);
            *(float4*)&Wsh[d4] = make_float4(a0.x+b0.x, a0.y+b0.y, a1.x+b1.x, a1.y+b1.y);
        }
        __syncthreads();
        float4 wp = *(const float4*)&Wsh[VV + i0];
        float v0 = Wsh[tsh[i0+0]] + wp.x;
        float v1 = Wsh[tsh[i0+1]] + wp.y;
        float v2 = Wsh[tsh[i0+2]] + wp.z;
        float v3 = Wsh[tsh[i0+3]] + wp.w;
        __nv_bfloat162 o0 = __floats2bfloat162_rn(v0, v1);
        __nv_bfloat162 o1 = __floats2bfloat162_rn(v2, v3);
        uint2 out; out.x = *(uint32_t*)&o0; out.y = *(uint32_t*)&o1;
        *(uint2*)(S + ((size_t)b*NN + m)*NN + i0) = out;
    }
}

// ---------------------------------------------------------------------------
// Causal row softmax: register-resident; zero-writes trimmed to diag tile.
// ---------------------------------------------------------------------------
__global__ void __launch_bounds__(256)
softmax_causal(const bf16* __restrict__ S, bf16* __restrict__ A) {
    int b = blockIdx.y, n = blockIdx.x;
    __shared__ float rs[8];
    const bf16* srow = S + ((size_t)b*NN + n)*NN;
    bf16*       arow = A + ((size_t)b*NN + n)*NN;
    int t = threadIdx.x;
    int i0 = t*4;
    float v[4] = { -1e30f, -1e30f, -1e30f, -1e30f };
    if (i0 <= n) {
        uint2 raw = *(const uint2*)(srow + i0);
        float2 f0 = bf2f(raw.x);
        float2 f1 = bf2f(raw.y);
        v[0] = f0.x;
        if (i0+1 <= n) v[1] = f0.y;
        if (i0+2 <= n) v[2] = f1.x;
        if (i0+3 <= n) v[3] = f1.y;
    }
    float mx = blk_max(fmaxf(fmaxf(v[0], v[1]), fmaxf(v[2], v[3])), rs, t);
    __syncthreads();
    float e[4];
    #pragma unroll
    for (int k = 0; k < 4; k++)
        e[k] = (i0+k <= n) ? __expf(v[k] - mx) : 0.f;
    float sum = blk_sum(e[0]+e[1]+e[2]+e[3], rs, t);
    float inv = 1.f / sum;
    int kmax = ((n >> 7) + 1) << 7;
    if (i0 < kmax) {
        __nv_bfloat162 o0 = __floats2bfloat162_rn(e[0]*inv, e[1]*inv);
        __nv_bfloat162 o1 = __floats2bfloat162_rn(e[2]*inv, e[3]*inv);
        uint2 out; out.x = *(uint32_t*)&o0; out.y = *(uint32_t*)&o1;
        *(uint2*)(arow + i0) = out;
    }
}

// ---------------------------------------------------------------------------
// Batched bf16 GEMM: mma.sync m16n8k16, ldmatrix, 3-stage cp.async.
// ALL modes triangular (bj <= bi); bi reversed (heavy tiles first).
// MODE 0: C = A*B      k in [0,(bi+1)*128)
// MODE 1: C = A*B^T    k in [0,(bj+1)*128)
// MODE 2: C = A*B      k in [bj*128,(bi+1)*128),  zero strict-upper entries
// ---------------------------------------------------------------------------
#define ASTG_H (128*40)
template<int MODE>
struct BC { static constexpr int STR = 136, STG = 32*136; };
template<> struct BC<1> { static constexpr int STR = 40, STG = 128*40; };

template<int MODE>
__global__ void __launch_bounds__(256)
gemm_bf16(const bf16* __restrict__ Ag, const bf16* __restrict__ Bg,
          bf16* __restrict__ Cg) {
    constexpr int BSTR = BC<MODE>::STR;
    constexpr int BSTG = BC<MODE>::STG;
    int bi = (int)gridDim.y - 1 - (int)blockIdx.y;   // heavy tiles first
    int bj = blockIdx.x, b = blockIdx.z;
    if (bj > bi) return;
    const bf16* Ab = Ag + (size_t)b*NN*NN;
    const bf16* Bb = Bg + (size_t)b*NN*NN;
    bf16*       Cb = Cg + (size_t)b*NN*NN;
    int k0 = (MODE == 2) ? bj*128 : 0;
    int k1 = (MODE == 1) ? (bj+1)*128 : (bi+1)*128;

    extern __shared__ __align__(16) bf16 sm[];
    uint32_t smbase = (uint32_t)__cvta_generic_to_shared(sm);
    uint32_t AB = smbase;
    uint32_t BBs = smbase + 3*ASTG_H*2;

    int tid  = threadIdx.x;
    int wid  = tid >> 5, lane = tid & 31;
    int gid  = lane >> 2, tig = lane & 3;
    int g    = lane >> 3, rsel = lane & 7;
    int wm   = (wid & 3) * 32;
    int wn   = (wid >> 2) * 64;
    int row0 = bi*128, col0 = bj*128;

    float c[2][8][4] = {};

    auto load_stage = [&](int s, int kb) {
        uint32_t Ad = AB + (s*ASTG_H)*2;
        #pragma unroll
        for (int h = 0; h < 2; h++) {
            int chunk = tid + 256*h;
            int r = chunk >> 2, c8 = (chunk & 3) * 8;
            uint32_t dst = Ad + (r*40 + c8)*2;
            const bf16* src = &Ab[(size_t)(row0 + r)*NN + kb + c8];
            asm volatile("cp.async.ca.shared.global [%0], [%1], 16;\n" :: "r"(dst), "l"(src));
        }
        uint32_t Bd = BBs + (s*BSTG)*2;
        if (MODE == 1) {
            #pragma unroll
            for (int h = 0; h < 2; h++) {
                int chunk = tid + 256*h;
                int r = chunk >> 2, c8 = (chunk & 3) * 8;
                uint32_t dst = Bd + (r*BSTR + c8)*2;
                const bf16* src = &Bb[(size_t)(col0 + r)*NN + kb + c8];
                asm volatile("cp.async.ca.shared.global [%0], [%1], 16;\n" :: "r"(dst), "l"(src));
            }
        } else {
            #pragma unroll
            for (int h = 0; h < 2; h++) {
                int chunk = tid + 256*h;
                int r = chunk >> 4, c8 = (chunk & 15) * 8;
                uint32_t dst = Bd + (r*BSTR + c8)*2;
                const bf16* src = &Bb[(size_t)(kb + r)*NN + col0 + c8];
                asm volatile("cp.async.ca.shared.global [%0], [%1], 16;\n" :: "r"(dst), "l"(src));
            }
        }
    };

    auto compute = [&](int s) {
        uint32_t Ac = AB + (s*ASTG_H)*2;
        uint32_t Bc = BBs + (s*BSTG)*2;
        #pragma unroll
        for (int kk = 0; kk < 32; kk += 16) {
            uint32_t a[2][4];
            #pragma unroll
            for (int i = 0; i < 2; i++) {
                int row = wm + i*16 + (g & 1)*8 + rsel;
                int col = kk + (g >> 1)*8;
                uint32_t addr = Ac + (row*40 + col)*2;
                asm volatile("ldmatrix.sync.aligned.m8n8.x4.shared.b16 {%0,%1,%2,%3}, [%4];"
                             : "=r"(a[i][0]), "=r"(a[i][1]), "=r"(a[i][2]), "=r"(a[i][3])
                             : "r"(addr));
            }
            uint32_t bfr[8][2];
            #pragma unroll
            for (int u = 0; u < 4; u++) {
                int n0 = wn + u*16;
                uint32_t r0, r1, r2, r3;
                if (MODE == 1) {
                    int n = n0 + (g >> 1)*8 + rsel;
                    int k = kk + (g & 1)*8;
                    uint32_t addr = Bc + (n*BSTR + k)*2;
                    asm volatile("ldmatrix.sync.aligned.m8n8.x4.shared.b16 {%0,%1,%2,%3}, [%4];"
                                 : "=r"(r0), "=r"(r1), "=r"(r2), "=r"(r3) : "r"(addr));
                } else {
                    int k = kk + (g & 1)*8 + rsel;
                    int n = n0 + (g >> 1)*8;
                    uint32_t addr = Bc + (k*BSTR + n)*2;
                    asm volatile("ldmatrix.sync.aligned.m8n8.x4.trans.shared.b16 {%0,%1,%2,%3}, [%4];"
                                 : "=r"(r0), "=r"(r1), "=r"(r2), "=r"(r3) : "r"(addr));
                }
                bfr[2*u  ][0] = r0; bfr[2*u  ][1] = r1;
                bfr[2*u+1][0] = r2; bfr[2*u+1][1] = r3;
            }
            #pragma unroll
            for (int i = 0; i < 2; i++)
                #pragma unroll
                for (int j = 0; j < 8; j++) {
                    asm volatile(
                        "mma.sync.aligned.m16n8k16.row.col.f32.bf16.bf16.f32 "
                        "{%0,%1,%2,%3}, {%4,%5,%6,%7}, {%8,%9}, {%0,%1,%2,%3};"
                        : "+f"(c[i][j][0]), "+f"(c[i][j][1]),
                          "+f"(c[i][j][2]), "+f"(c[i][j][3])
                        : "r"(a[i][0]), "r"(a[i][1]), "r"(a[i][2]), "r"(a[i][3]),
                          "r"(bfr[j][0]), "r"(bfr[j][1]));
                }
        }
    };

    int nslab = (k1 - k0) >> 5;
    load_stage(0, k0);
    asm volatile("cp.async.commit_group;\n");
    load_stage(1, k0 + 32);
    asm volatile("cp.async.commit_group;\n");

    int sc = 0, sl = 2;
    for (int t = 0; t < nslab - 1; t++) {
        asm volatile("cp.async.wait_group 1;\n");
        __syncthreads();
        if (t + 2 < nslab) {
            load_stage(sl, k0 + (t+2)*32);
            asm volatile("cp.async.commit_group;\n");
            sl = (sl == 2) ? 0 : sl + 1;
        }
        compute(sc);
        sc = (sc == 2) ? 0 : sc + 1;
    }
    asm volatile("cp.async.wait_group 0;\n");
    __syncthreads();
    compute(sc);

    #pragma unroll
    for (int i = 0; i < 2; i++) {
        #pragma unroll
        for (int j = 0; j < 8; j++) {
            int gc = col0 + wn + j*8 + tig*2;
            #pragma unroll
            for (int h = 0; h < 2; h++) {
                int gr = row0 + wm + i*16 + gid + h*8;
                float vx = c[i][j][h*2], vy = c[i][j][h*2+1];
                if (MODE == 2) {
                    if (gc+0 > gr) vx = 0.f;
                    if (gc+1 > gr) vy = 0.f;
                }
                __nv_bfloat162 v = __floats2bfloat162_rn(vx, vy);
                *(__nv_bfloat162*)&Cb[(size_t)gr*NN + gc] = v;
            }
        }
    }
}

// ---------------------------------------------------------------------------
// Layer-4 matvec helpers (P4 = A3*P3 never materialized).
// colmv: out[k] = sum_{m >= k&~127} vec[m] * M[m,k]   (column traversal)
//   VECBF: vec = row NN-1 of the bf16 matrix passed as 'vec'; else float array.
// rowmv: out[n] = sum_{k < roundup(n+1,128)} M[n,k] * vec[k]
// Causal tile starts guarantee unwritten upper-tile garbage is never read.
// ---------------------------------------------------------------------------
template<bool VECBF>
__global__ void __launch_bounds__(256)
l4_colmv(const bf16* __restrict__ M, const void* __restrict__ vec,
         float* __restrict__ outv) {
    int b = blockIdx.y;
    int k = blockIdx.x*512 + threadIdx.x*2;
    __shared__ float ash[NN];
    for (int i = threadIdx.x; i < NN; i += 256) {
        if (VECBF)
            ash[i] = __bfloat162float(((const bf16*)vec)[((size_t)b*NN + (NN-1))*NN + i]);
        else
            ash[i] = ((const float*)vec)[b*NN + i];
    }
    __syncthreads();
    const bf16* Mb = M + (size_t)b*NN*NN;
    int kt0 = k & ~127;
    float a0 = 0.f, a1 = 0.f;
    for (int m = kt0; m < NN; m++) {
        float2 mv = bf2f(*(const uint32_t*)&Mb[(size_t)m*NN + k]);
        float vm = ash[m];
        a0 += vm*mv.x; a1 += vm*mv.y;
    }
    outv[b*NN + k]   = a0;
    outv[b*NN + k+1] = a1;
}

__global__ void __launch_bounds__(256)
l4_rowmv(const bf16* __restrict__ M, const float* __restrict__ vec,
         float* __restrict__ outv) {
    int b = blockIdx.y;
    __shared__ float ush[NN];
    for (int i = threadIdx.x; i < NN; i += 256) ush[i] = vec[b*NN + i];
    __syncthreads();
    int row  = blockIdx.x * 8 + (threadIdx.x >> 5);
    int lane = threadIdx.x & 31;
    int kmax = ((row >> 7) + 1) << 7;
    const bf16* Mr = M + ((size_t)b*NN + row)*NN;
    float acc = 0.f;
    for (int kk = lane*2; kk < kmax; kk += 64) {
        float2 mv = bf2f(*(const uint32_t*)&Mr[kk]);
        acc += ush[kk]*mv.x + ush[kk+1]*mv.y;
    }
    for (int o = 16; o; o >>= 1) acc += __shfl_down_sync(0xffffffffu, acc, o);
    if (lane == 0) outv[b*NN + row] = acc;
}

// ---------------------------------------------------------------------------
// Layer 4 q-chain + logits
// ---------------------------------------------------------------------------
__global__ void __launch_bounds__(384)
l4_q_part(const bf16* __restrict__ Rb, const int* __restrict__ tok,
          const float* __restrict__ r4, float* __restrict__ qp) {
    int b = blockIdx.y, bm = blockIdx.x;
    __shared__ float rsh[32];
    __shared__ int   tsh[32];
    int t = threadIdx.x;
    if (t < 32) {
        int m = bm*32 + t;
        rsh[t] = r4[b*NN + m];
        tsh[t] = tok[b*NN + m];
    }
    __syncthreads();
    int d0 = t*4;
    float acc[4] = {};
    #pragma unroll 4
    for (int j = 0; j < 32; j++) {
        int m = bm*32 + j;
        float r = rsh[j];
        uint2 u0 = *(const uint2*)(Rb + (size_t)tsh[j]*DD + d0);
        uint2 u1 = *(const uint2*)(Rb + (size_t)(VV + m)*DD + d0);
        float2 a0 = bf2f(u0.x), a1 = bf2f(u0.y);
        float2 b0 = bf2f(u1.x), b1 = bf2f(u1.y);
        acc[0] += r * (a0.x + b0.x);
        acc[1] += r * (a0.y + b0.y);
        acc[2] += r * (a1.x + b1.x);
        acc[3] += r * (a1.y + b1.y);
    }
    *(float4*)&qp[((size_t)b*32 + bm)*DD + d0] = make_float4(acc[0], acc[1], acc[2], acc[3]);
}

__global__ void __launch_bounds__(512)
l4_q_reduce(const float* __restrict__ qp, const int* __restrict__ tok,
            float* __restrict__ u) {
    int b = blockIdx.x;
    __shared__ float qsh[DD];
    int t = threadIdx.x;
    for (int d = t; d < DD; d += 512) {
        float acc = 0.f;
        #pragma unroll 8
        for (int bm = 0; bm < 32; bm++)
            acc += qp[((size_t)b*32 + bm)*DD + d];
        qsh[d] = acc;
    }
    __syncthreads();
    for (int m = t; m < NN; m += 512)
        u[b*NN + m] = qsh[tok[b*NN + m]] + qsh[VV + m];
}

__global__ void l4_softmax(const float* __restrict__ s, float* __restrict__ a) {
    int b = blockIdx.x;
    __shared__ float rs[8];
    int t = threadIdx.x;
    int i0 = t*4;
    float4 v4 = *(const float4*)&s[b*NN + i0];
    float v[4] = { v4.x, v4.y, v4.z, v4.w };
    float mx = blk_max(fmaxf(fmaxf(v[0], v[1]), fmaxf(v[2], v[3])), rs, t);
    __syncthreads();
    float e[4];
    #pragma unroll
    for (int k = 0; k < 4; k++) e[k] = __expf(v[k] - mx);
    float sum = blk_sum(e[0]+e[1]+e[2]+e[3], rs, t);
    float inv = 1.f / sum;
    *(float4*)&a[b*NN + i0] = make_float4(e[0]*inv, e[1]*inv, e[2]*inv, e[3]*inv);
}

__global__ void l4_c(const int* __restrict__ tok, const float* __restrict__ p,
                     float* __restrict__ c) {
    int b = blockIdx.x;
    __shared__ float psh[NN];
    __shared__ int   tsh[NN];
    for (int i = threadIdx.x; i < NN; i += blockDim.x) {
        psh[i] = p[b*NN + i];
        tsh[i] = tok[b*NN + i];
    }
    __syncthreads();
    int w = threadIdx.x;  // blockDim.x == 512 == VV
    float acc = 0.f;
    for (int m = 0; m < NN; m++)
        if (tsh[m] == w) acc += psh[m];
    c[b*VV + w] = acc;
}

__global__ void l4_logits(const float* __restrict__ c, const float* __restrict__ p,
                          const float* __restrict__ U, float* __restrict__ out) {
    int b = blockIdx.y;
    __shared__ float hsh[DD];
    for (int i = threadIdx.x; i < VV; i += 256) hsh[i]      = c[b*VV + i];
    for (int i = threadIdx.x; i < NN; i += 256) hsh[VV + i] = p[b*NN + i];
    __syncthreads();
    int wid = threadIdx.x >> 5, lane = threadIdx.x & 31;
    int v = blockIdx.x * 8 + wid;
    const float* Ur = U + (size_t)v*DD;
    float acc = 0.f;
    for (int j = lane; j < DD; j += 32) acc += hsh[j] * Ur[j];
    for (int o = 16; o; o >>= 1) acc += __shfl_down_sync(0xffffffffu, acc, o);
    if (lane == 0) out[b*VV + v] = acc;
}

// ---------------------------------------------------------------------------
extern "C" void kernel_launch(void* const* d_in, const int* in_sizes, int n_in,
                              void* d_out, int out_size) {
    const int*   tok = (const int*)  d_in[0];
    const float* R   = (const float*)d_in[1];
    const float* U   = (const float*)d_in[2];
    float*       out = (float*)d_out;

    bf16 *Rb, *S, *P, *T, *A, *PN;
    float *qp, *u, *r4, *w, *sr, *a, *bv, *p, *c;
    cudaGetSymbolAddress((void**)&Rb, g_Rb);
    cudaGetSymbolAddress((void**)&S,  g_S);
    cudaGetSymbolAddress((void**)&P,  g_P);
    cudaGetSymbolAddress((void**)&T,  g_T);
    cudaGetSymbolAddress((void**)&A,  g_A);
    cudaGetSymbolAddress((void**)&PN, g_PN);
    cudaGetSymbolAddress((void**)&qp, g_qp);
    cudaGetSymbolAddress((void**)&u,  g_u);
    cudaGetSymbolAddress((void**)&r4, g_r4);
    cudaGetSymbolAddress((void**)&w,  g_w);
    cudaGetSymbolAddress((void**)&sr, g_sr);
    cudaGetSymbolAddress((void**)&a,  g_a);
    cudaGetSymbolAddress((void**)&bv, g_bv);
    cudaGetSymbolAddress((void**)&p,  g_p);
    cudaGetSymbolAddress((void**)&c,  g_c);

    const int SM0 = (3*ASTG_H + 3*BC<0>::STG) * 2;
    const int SM1 = (3*ASTG_H + 3*BC<1>::STG) * 2;
    cudaFuncSetAttribute(gemm_bf16<0>, cudaFuncAttributeMaxDynamicSharedMemorySize, SM0);
    cudaFuncSetAttribute(gemm_bf16<1>, cudaFuncAttributeMaxDynamicSharedMemorySize, SM1);
    cudaFuncSetAttribute(gemm_bf16<2>, cudaFuncAttributeMaxDynamicSharedMemorySize, SM0);

    dim3 gRow(NN, BB), gRow4(NN/4, BB), gT(8, 8, BB);
    dim3 gCol(2, BB), gRowMV(128, BB);
    const size_t RS = (size_t)DD*DD;

    // R layer 0 -> bf16, then layer-1 fused (rows + conv of R layers 1..3)
    r_conv0  <<<(DD*DD)/1024, 256>>>(R, Rb);
    gsm1_conv<<<dim3(256, 32 + 27), 256>>>(R, Rb, tok, P);

    // Layer 2: scores = P*S2*P^T ; A2 = softmax ; P3 = A2*P
    gather_S      <<<gRow4, 256>>>(Rb + 1*RS, tok, S);
    gemm_bf16<0>  <<<gT, 256, SM0>>>(P, S, T);
    gemm_bf16<1>  <<<gT, 256, SM1>>>(T, P, A);
    softmax_causal<<<gRow, 256>>>(A, A);
    gemm_bf16<2>  <<<gT, 256, SM0>>>(A, P, PN);

    // Layer 3: scores = P3*S3*P3^T ; A3 = softmax  (P4 never materialized)
    gather_S      <<<gRow4, 256>>>(Rb + 2*RS, tok, S);
    gemm_bf16<0>  <<<gT, 256, SM0>>>(PN, S, T);
    gemm_bf16<1>  <<<gT, 256, SM1>>>(T, PN, A);
    softmax_causal<<<gRow, 256>>>(A, A);

    // Layer 4 via decomposition: P4 = A3*P3
    l4_colmv<true ><<<gCol, 256>>>(PN, A, r4);        // r4 = A3[1023,:]*P3
    l4_q_part      <<<dim3(32, BB), 384>>>(Rb + 3*RS, tok, r4, qp);
    l4_q_reduce    <<<BB, 512>>>(qp, tok, u);
    l4_rowmv       <<<gRowMV, 256>>>(PN, u, w);       // w = P3*u
    l4_rowmv       <<<gRowMV, 256>>>(A, w, sr);       // srow = A3*w
    l4_softmax     <<<BB, 256>>>(sr, a);
    l4_colmv<false><<<gCol, 256>>>(A, a, bv);         // b = a^T*A3
    l4_colmv<false><<<gCol, 256>>>(PN, bv, p);        // p = b^T*P3
    l4_c           <<<BB, 512>>>(tok, p, c);
    l4_logits      <<<dim3(64, BB), 256>>>(c, p, U, out);
}

// round 15
// speedup vs baseline: 1.1153x; 1.1153x over previous
#include <cuda_runtime.h>
#include <cuda_bf16.h>
#include <cstdint>

// Problem constants
#define BB 32
#define NN 1024
#define VV 512
#define DD 1536

typedef __nv_bfloat16 bf16;

// Scratch buffers (allocation-free rule: __device__ globals). Big tensors bf16.
__device__ bf16  g_Rb[(size_t)4*DD*DD];   // bf16 copy of R (all layers)
__device__ bf16  g_S [(size_t)BB*NN*NN];
__device__ bf16  g_P [(size_t)BB*NN*NN];
__device__ bf16  g_T [(size_t)BB*NN*NN];
__device__ bf16  g_A [(size_t)BB*NN*NN];
__device__ bf16  g_PN[(size_t)BB*NN*NN];
__device__ float g_qp[(size_t)BB*32*DD];
__device__ float g_u [BB*NN];
__device__ float g_sr[BB*NN];
__device__ float g_a [BB*NN];
__device__ float g_p [BB*NN];
__device__ float g_c [BB*VV];

__device__ __forceinline__ float2 bf2f(uint32_t u) {
    return __bfloat1622float2(*(__nv_bfloat162*)&u);
}

// Block-wide reductions over 8 warps (256 threads), value broadcast to all.
__device__ __forceinline__ float blk_max(float v, float* rs, int t) {
    #pragma unroll
    for (int o = 16; o; o >>= 1) v = fmaxf(v, __shfl_xor_sync(0xffffffffu, v, o));
    if ((t & 31) == 0) rs[t >> 5] = v;
    __syncthreads();
    float r = rs[0];
    #pragma unroll
    for (int w = 1; w < 8; w++) r = fmaxf(r, rs[w]);
    return r;
}
__device__ __forceinline__ float blk_sum(float v, float* rs, int t) {
    #pragma unroll
    for (int o = 16; o; o >>= 1) v += __shfl_xor_sync(0xffffffffu, v, o);
    if ((t & 31) == 0) rs[t >> 5] = v;
    __syncthreads();
    float r = rs[0];
    #pragma unroll
    for (int w = 1; w < 8; w++) r += rs[w];
    return r;
}

__device__ __forceinline__ void conv_chunk(const float* __restrict__ src,
                                           bf16* __restrict__ dst, size_t i) {
    float4 v = *(const float4*)(src + i);
    __nv_bfloat162 o0 = __floats2bfloat162_rn(v.x, v.y);
    __nv_bfloat162 o1 = __floats2bfloat162_rn(v.z, v.w);
    uint2 out; out.x = *(uint32_t*)&o0; out.y = *(uint32_t*)&o1;
    *(uint2*)(dst + i) = out;
}

// ---------------------------------------------------------------------------
// R layer-0 -> bf16 (small; runs before gsm1_conv)
// ---------------------------------------------------------------------------
__global__ void r_conv0(const float* __restrict__ R, bf16* __restrict__ Rb) {
    conv_chunk(R, Rb, ((size_t)blockIdx.x * 256 + threadIdx.x) * 4);
}

// ---------------------------------------------------------------------------
// Fused layer 1 (4 rows/block) + R layers 1-3 conversion merged in.
// Zero-writes trimmed to the diagonal 128-tile (all consumers respect bounds).
// ---------------------------------------------------------------------------
__global__ void __launch_bounds__(256)
gsm1_conv(const float* __restrict__ R, bf16* __restrict__ Rb,
          const int* __restrict__ tok, bf16* __restrict__ P) {
    int t = threadIdx.x;
    if (blockIdx.y >= 32) {                    // convert R layers 1..3
        size_t cidx = ((size_t)(blockIdx.y - 32) * 256 + blockIdx.x);
        size_t i = (size_t)DD*DD + cidx*1024 + t*4;
        conv_chunk(R, Rb, i);
        return;
    }
    int b = blockIdx.y;
    __shared__ float Wsh[DD];
    __shared__ int   tsh[NN];
    __shared__ float rs[8];
    const int* tb = tok + b*NN;
    for (int i = t; i < NN; i += 256) tsh[i] = tb[i];
    int i0 = t*4;
    #pragma unroll
    for (int r = 0; r < 4; r++) {
        int m = blockIdx.x*4 + r;
        __syncthreads();
        int tm = tb[m];
        const bf16* r0 = Rb + (size_t)tm*DD;
        const bf16* r1 = Rb + (size_t)(VV + m)*DD;
        for (int d4 = t*4; d4 < DD; d4 += 1024) {
            uint2 u0 = *(const uint2*)(r0 + d4);
            uint2 u1 = *(const uint2*)(r1 + d4);
            float2 a0 = bf2f(u0.x), a1 = bf2f(u0.y);
            float2 b0 = bf2f(u1.x), b1 = bf2f(u1.y);
            *(float4*)&Wsh[d4] = make_float4(a0.x+b0.x, a0.y+b0.y, a1.x+b1.x, a1.y+b1.y);
        }
        __syncthreads();
        float v[4];
        #pragma unroll
        for (int k = 0; k < 4; k++)
            v[k] = (i0+k <= m) ? (Wsh[tsh[i0+k]] + Wsh[VV + i0+k]) : -1e30f;
        float mx = blk_max(fmaxf(fmaxf(v[0], v[1]), fmaxf(v[2], v[3])), rs, t);
        __syncthreads();
        float e[4];
        #pragma unroll
        for (int k = 0; k < 4; k++)
            e[k] = (i0+k <= m) ? __expf(v[k] - mx) : 0.f;
        float sum = blk_sum(e[0]+e[1]+e[2]+e[3], rs, t);
        float inv = 1.f / sum;
        int kmax = ((m >> 7) + 1) << 7;
        if (i0 < kmax) {
            __nv_bfloat162 o0 = __floats2bfloat162_rn(e[0]*inv, e[1]*inv);
            __nv_bfloat162 o1 = __floats2bfloat162_rn(e[2]*inv, e[3]*inv);
            uint2 out; out.x = *(uint32_t*)&o0; out.y = *(uint32_t*)&o1;
            *(uint2*)(P + ((size_t)b*NN + m)*NN + i0) = out;
        }
    }
}

// ---------------------------------------------------------------------------
// S_k gather: 4 rows per block, 8B vector loads/stores.
// ---------------------------------------------------------------------------
__global__ void __launch_bounds__(256)
gather_S(const bf16* __restrict__ Rb, const int* __restrict__ tok,
         bf16* __restrict__ S) {
    int b = blockIdx.y;
    __shared__ float Wsh[DD];
    __shared__ int   tsh[NN];
    const int* tb = tok + b*NN;
    int t = threadIdx.x;
    for (int i = t; i < NN; i += 256) tsh[i] = tb[i];
    int i0 = t*4;
    #pragma unroll
    for (int r = 0; r < 4; r++) {
        int m = blockIdx.x*4 + r;
        __syncthreads();
        int tm = tb[m];
        const bf16* r0 = Rb + (size_t)tm*DD;
        const bf16* r1 = Rb + (size_t)(VV + m)*DD;
        for (int d4 = t*4; d4 < DD; d4 += 1024) {
            uint2 u0 = *(const uint2*)(r0 + d4);
            uint2 u1 = *(const uint2*)(r1 + d4);
            float2 a0 = bf2f(u0.x), a1 = bf2f(u0.y);
            float2 b0 = bf2f(u1.x), b1 = bf2f(u1.y);
            *(float4*)&Wsh[d4] = make_float4(a0.x+b0.x, a0.y+b0.y, a1.x+b1.x, a1.y+b1.y);
        }
        __syncthreads();
        float4 wp = *(const float4*)&Wsh[VV + i0];
        float v0 = Wsh[tsh[i0+0]] + wp.x;
        float v1 = Wsh[tsh[i0+1]] + wp.y;
        float v2 = Wsh[tsh[i0+2]] + wp.z;
        float v3 = Wsh[tsh[i0+3]] + wp.w;
        __nv_bfloat162 o0 = __floats2bfloat162_rn(v0, v1);
        __nv_bfloat162 o1 = __floats2bfloat162_rn(v2, v3);
        uint2 out; out.x = *(uint32_t*)&o0; out.y = *(uint32_t*)&o1;
        *(uint2*)(S + ((size_t)b*NN + m)*NN + i0) = out;
    }
}

// ---------------------------------------------------------------------------
// Causal row softmax: register-resident; zero-writes trimmed to diag tile.
// ---------------------------------------------------------------------------
__global__ void __launch_bounds__(256)
softmax_causal(const bf16* __restrict__ S, bf16* __restrict__ A) {
    int b = blockIdx.y, n = blockIdx.x;
    __shared__ float rs[8];
    const bf16* srow = S + ((size_t)b*NN + n)*NN;
    bf16*       arow = A + ((size_t)b*NN + n)*NN;
    int t = threadIdx.x;
    int i0 = t*4;
    float v[4] = { -1e30f, -1e30f, -1e30f, -1e30f };
    if (i0 <= n) {
        uint2 raw = *(const uint2*)(srow + i0);
        float2 f0 = bf2f(raw.x);
        float2 f1 = bf2f(raw.y);
        v[0] = f0.x;
        if (i0+1 <= n) v[1] = f0.y;
        if (i0+2 <= n) v[2] = f1.x;
        if (i0+3 <= n) v[3] = f1.y;
    }
    float mx = blk_max(fmaxf(fmaxf(v[0], v[1]), fmaxf(v[2], v[3])), rs, t);
    __syncthreads();
    float e[4];
    #pragma unroll
    for (int k = 0; k < 4; k++)
        e[k] = (i0+k <= n) ? __expf(v[k] - mx) : 0.f;
    float sum = blk_sum(e[0]+e[1]+e[2]+e[3], rs, t);
    float inv = 1.f / sum;
    int kmax = ((n >> 7) + 1) << 7;
    if (i0 < kmax) {
        __nv_bfloat162 o0 = __floats2bfloat162_rn(e[0]*inv, e[1]*inv);
        __nv_bfloat162 o1 = __floats2bfloat162_rn(e[2]*inv, e[3]*inv);
        uint2 out; out.x = *(uint32_t*)&o0; out.y = *(uint32_t*)&o1;
        *(uint2*)(arow + i0) = out;
    }
}

// ---------------------------------------------------------------------------
// Batched bf16 GEMM: mma.sync m16n8k16, ldmatrix, 3-stage cp.async.
// ALL modes triangular (bj <= bi); bi reversed (heavy tiles first).
// MODE 0: C = A*B      k in [0,(bi+1)*128)
// MODE 1: C = A*B^T    k in [0,(bj+1)*128)
// MODE 2: C = A*B      k in [bj*128,(bi+1)*128),  zero strict-upper entries
// ---------------------------------------------------------------------------
#define ASTG_H (128*40)
template<int MODE>
struct BC { static constexpr int STR = 136, STG = 32*136; };
template<> struct BC<1> { static constexpr int STR = 40, STG = 128*40; };

template<int MODE>
__global__ void __launch_bounds__(256)
gemm_bf16(const bf16* __restrict__ Ag, const bf16* __restrict__ Bg,
          bf16* __restrict__ Cg) {
    constexpr int BSTR = BC<MODE>::STR;
    constexpr int BSTG = BC<MODE>::STG;
    int bi = (int)gridDim.y - 1 - (int)blockIdx.y;   // heavy tiles first
    int bj = blockIdx.x, b = blockIdx.z;
    if (bj > bi) return;
    const bf16* Ab = Ag + (size_t)b*NN*NN;
    const bf16* Bb = Bg + (size_t)b*NN*NN;
    bf16*       Cb = Cg + (size_t)b*NN*NN;
    int k0 = (MODE == 2) ? bj*128 : 0;
    int k1 = (MODE == 1) ? (bj+1)*128 : (bi+1)*128;

    extern __shared__ __align__(16) bf16 sm[];
    uint32_t smbase = (uint32_t)__cvta_generic_to_shared(sm);
    uint32_t AB = smbase;
    uint32_t BBs = smbase + 3*ASTG_H*2;

    int tid  = threadIdx.x;
    int wid  = tid >> 5, lane = tid & 31;
    int gid  = lane >> 2, tig = lane & 3;
    int g    = lane >> 3, rsel = lane & 7;
    int wm   = (wid & 3) * 32;
    int wn   = (wid >> 2) * 64;
    int row0 = bi*128, col0 = bj*128;

    float c[2][8][4] = {};

    auto load_stage = [&](int s, int kb) {
        uint32_t Ad = AB + (s*ASTG_H)*2;
        #pragma unroll
        for (int h = 0; h < 2; h++) {
            int chunk = tid + 256*h;
            int r = chunk >> 2, c8 = (chunk & 3) * 8;
            uint32_t dst = Ad + (r*40 + c8)*2;
            const bf16* src = &Ab[(size_t)(row0 + r)*NN + kb + c8];
            asm volatile("cp.async.ca.shared.global [%0], [%1], 16;\n" :: "r"(dst), "l"(src));
        }
        uint32_t Bd = BBs + (s*BSTG)*2;
        if (MODE == 1) {
            #pragma unroll
            for (int h = 0; h < 2; h++) {
                int chunk = tid + 256*h;
                int r = chunk >> 2, c8 = (chunk & 3) * 8;
                uint32_t dst = Bd + (r*BSTR + c8)*2;
                const bf16* src = &Bb[(size_t)(col0 + r)*NN + kb + c8];
                asm volatile("cp.async.ca.shared.global [%0], [%1], 16;\n" :: "r"(dst), "l"(src));
            }
        } else {
            #pragma unroll
            for (int h = 0; h < 2; h++) {
                int chunk = tid + 256*h;
                int r = chunk >> 4, c8 = (chunk & 15) * 8;
                uint32_t dst = Bd + (r*BSTR + c8)*2;
                const bf16* src = &Bb[(size_t)(kb + r)*NN + col0 + c8];
                asm volatile("cp.async.ca.shared.global [%0], [%1], 16;\n" :: "r"(dst), "l"(src));
            }
        }
    };

    auto compute = [&](int s) {
        uint32_t Ac = AB + (s*ASTG_H)*2;
        uint32_t Bc = BBs + (s*BSTG)*2;
        #pragma unroll
        for (int kk = 0; kk < 32; kk += 16) {
            uint32_t a[2][4];
            #pragma unroll
            for (int i = 0; i < 2; i++) {
                int row = wm + i*16 + (g & 1)*8 + rsel;
                int col = kk + (g >> 1)*8;
                uint32_t addr = Ac + (row*40 + col)*2;
                asm volatile("ldmatrix.sync.aligned.m8n8.x4.shared.b16 {%0,%1,%2,%3}, [%4];"
                             : "=r"(a[i][0]), "=r"(a[i][1]), "=r"(a[i][2]), "=r"(a[i][3])
                             : "r"(addr));
            }
            uint32_t bfr[8][2];
            #pragma unroll
            for (int u = 0; u < 4; u++) {
                int n0 = wn + u*16;
                uint32_t r0, r1, r2, r3;
                if (MODE == 1) {
                    int n = n0 + (g >> 1)*8 + rsel;
                    int k = kk + (g & 1)*8;
                    uint32_t addr = Bc + (n*BSTR + k)*2;
                    asm volatile("ldmatrix.sync.aligned.m8n8.x4.shared.b16 {%0,%1,%2,%3}, [%4];"
                                 : "=r"(r0), "=r"(r1), "=r"(r2), "=r"(r3) : "r"(addr));
                } else {
                    int k = kk + (g & 1)*8 + rsel;
                    int n = n0 + (g >> 1)*8;
                    uint32_t addr = Bc + (k*BSTR + n)*2;
                    asm volatile("ldmatrix.sync.aligned.m8n8.x4.trans.shared.b16 {%0,%1,%2,%3}, [%4];"
                                 : "=r"(r0), "=r"(r1), "=r"(r2), "=r"(r3) : "r"(addr));
                }
                bfr[2*u  ][0] = r0; bfr[2*u  ][1] = r1;
                bfr[2*u+1][0] = r2; bfr[2*u+1][1] = r3;
            }
            #pragma unroll
            for (int i = 0; i < 2; i++)
                #pragma unroll
                for (int j = 0; j < 8; j++) {
                    asm volatile(
                        "mma.sync.aligned.m16n8k16.row.col.f32.bf16.bf16.f32 "
                        "{%0,%1,%2,%3}, {%4,%5,%6,%7}, {%8,%9}, {%0,%1,%2,%3};"
                        : "+f"(c[i][j][0]), "+f"(c[i][j][1]),
                          "+f"(c[i][j][2]), "+f"(c[i][j][3])
                        : "r"(a[i][0]), "r"(a[i][1]), "r"(a[i][2]), "r"(a[i][3]),
                          "r"(bfr[j][0]), "r"(bfr[j][1]));
                }
        }
    };

    int nslab = (k1 - k0) >> 5;
    load_stage(0, k0);
    asm volatile("cp.async.commit_group;\n");
    load_stage(1, k0 + 32);
    asm volatile("cp.async.commit_group;\n");

    int sc = 0, sl = 2;
    for (int t = 0; t < nslab - 1; t++) {
        asm volatile("cp.async.wait_group 1;\n");
        __syncthreads();
        if (t + 2 < nslab) {
            load_stage(sl, k0 + (t+2)*32);
            asm volatile("cp.async.commit_group;\n");
            sl = (sl == 2) ? 0 : sl + 1;
        }
        compute(sc);
        sc = (sc == 2) ? 0 : sc + 1;
    }
    asm volatile("cp.async.wait_group 0;\n");
    __syncthreads();
    compute(sc);

    #pragma unroll
    for (int i = 0; i < 2; i++) {
        #pragma unroll
        for (int j = 0; j < 8; j++) {
            int gc = col0 + wn + j*8 + tig*2;
            #pragma unroll
            for (int h = 0; h < 2; h++) {
                int gr = row0 + wm + i*16 + gid + h*8;
                float vx = c[i][j][h*2], vy = c[i][j][h*2+1];
                if (MODE == 2) {
                    if (gc+0 > gr) vx = 0.f;
                    if (gc+1 > gr) vy = 0.f;
                }
                __nv_bfloat162 v = __floats2bfloat162_rn(vx, vy);
                *(__nv_bfloat162*)&Cb[(size_t)gr*NN + gc] = v;
            }
        }
    }
}

// ---------------------------------------------------------------------------
// Layer 4 (row 1023 only) + logits. P4 materialized (round-13 structure);
// consumers use causal bounds (never touch unwritten upper tiles).
// ---------------------------------------------------------------------------
__global__ void __launch_bounds__(384)
l4_q_part(const bf16* __restrict__ Rb, const int* __restrict__ tok,
          const bf16* __restrict__ P, float* __restrict__ qp) {
    int b = blockIdx.y, bm = blockIdx.x;
    __shared__ float rsh[32];
    __shared__ int   tsh[32];
    int t = threadIdx.x;
    if (t < 32) {
        int m = bm*32 + t;
        rsh[t] = __bfloat162float(P[((size_t)b*NN + (NN-1))*NN + m]);
        tsh[t] = tok[b*NN + m];
    }
    __syncthreads();
    int d0 = t*4;
    float acc[4] = {};
    #pragma unroll 4
    for (int j = 0; j < 32; j++) {
        int m = bm*32 + j;
        float r = rsh[j];
        uint2 u0 = *(const uint2*)(Rb + (size_t)tsh[j]*DD + d0);
        uint2 u1 = *(const uint2*)(Rb + (size_t)(VV + m)*DD + d0);
        float2 a0 = bf2f(u0.x), a1 = bf2f(u0.y);
        float2 b0 = bf2f(u1.x), b1 = bf2f(u1.y);
        acc[0] += r * (a0.x + b0.x);
        acc[1] += r * (a0.y + b0.y);
        acc[2] += r * (a1.x + b1.x);
        acc[3] += r * (a1.y + b1.y);
    }
    *(float4*)&qp[((size_t)b*32 + bm)*DD + d0] = make_float4(acc[0], acc[1], acc[2], acc[3]);
}

__global__ void __launch_bounds__(512)
l4_q_reduce(const float* __restrict__ qp, const int* __restrict__ tok,
            float* __restrict__ u) {
    int b = blockIdx.x;
    __shared__ float qsh[DD];
    int t = threadIdx.x;
    for (int d = t; d < DD; d += 512) {
        float acc = 0.f;
        #pragma unroll 8
        for (int bm = 0; bm < 32; bm++)
            acc += qp[((size_t)b*32 + bm)*DD + d];
        qsh[d] = acc;
    }
    __syncthreads();
    for (int m = t; m < NN; m += 512)
        u[b*NN + m] = qsh[tok[b*NN + m]] + qsh[VV + m];
}

__global__ void l4_srow(const float* __restrict__ u, const bf16* __restrict__ P,
                        float* __restrict__ srow) {
    int b = blockIdx.y;
    __shared__ float ush[NN];
    for (int i = threadIdx.x; i < NN; i += 256) ush[i] = u[b*NN + i];
    __syncthreads();
    int row  = blockIdx.x * 8 + (threadIdx.x >> 5);
    int lane = threadIdx.x & 31;
    int kmax = ((row >> 7) + 1) << 7;        // causal bound
    const bf16* Prow = P + ((size_t)b*NN + row)*NN;
    float acc = 0.f;
    for (int kk = lane*2; kk < kmax; kk += 64) {
        float2 mv = bf2f(*(const uint32_t*)&Prow[kk]);
        acc += ush[kk]*mv.x + ush[kk+1]*mv.y;
    }
    for (int o = 16; o; o >>= 1) acc += __shfl_down_sync(0xffffffffu, acc, o);
    if (lane == 0) srow[b*NN + row] = acc;
}

__global__ void l4_softmax(const float* __restrict__ s, float* __restrict__ a) {
    int b = blockIdx.x;
    __shared__ float rs[8];
    int t = threadIdx.x;
    int i0 = t*4;
    float4 v4 = *(const float4*)&s[b*NN + i0];
    float v[4] = { v4.x, v4.y, v4.z, v4.w };
    float mx = blk_max(fmaxf(fmaxf(v[0], v[1]), fmaxf(v[2], v[3])), rs, t);
    __syncthreads();
    float e[4];
    #pragma unroll
    for (int k = 0; k < 4; k++) e[k] = __expf(v[k] - mx);
    float sum = blk_sum(e[0]+e[1]+e[2]+e[3], rs, t);
    float inv = 1.f / sum;
    *(float4*)&a[b*NN + i0] = make_float4(e[0]*inv, e[1]*inv, e[2]*inv, e[3]*inv);
}

__global__ void l4_p(const float* __restrict__ a, const bf16* __restrict__ P,
                     float* __restrict__ p) {
    int b = blockIdx.y;
    int k = blockIdx.x * 256 + threadIdx.x;
    __shared__ float ash[NN];
    for (int i = threadIdx.x; i < NN; i += 256) ash[i] = a[b*NN + i];
    __syncthreads();
    int m0 = k & ~127;                        // causal bound: P4[m,k]=0 for m<tile(k)
    float acc = 0.f;
    for (int m = m0; m < NN; m++)
        acc += ash[m] * __bfloat162float(P[((size_t)b*NN + m)*NN + k]);
    p[b*NN + k] = acc;
}

__global__ void l4_c(const int* __restrict__ tok, const float* __restrict__ p,
                     float* __restrict__ c) {
    int b = blockIdx.x;
    __shared__ float psh[NN];
    __shared__ int   tsh[NN];
    for (int i = threadIdx.x; i < NN; i += blockDim.x) {
        psh[i] = p[b*NN + i];
        tsh[i] = tok[b*NN + i];
    }
    __syncthreads();
    int w = threadIdx.x;  // blockDim.x == 512 == VV
    float acc = 0.f;
    for (int m = 0; m < NN; m++)
        if (tsh[m] == w) acc += psh[m];
    c[b*VV + w] = acc;
}

__global__ void l4_logits(const float* __restrict__ c, const float* __restrict__ p,
                          const float* __restrict__ U, float* __restrict__ out) {
    int b = blockIdx.y;
    __shared__ float hsh[DD];
    for (int i = threadIdx.x; i < VV; i += 256) hsh[i]      = c[b*VV + i];
    for (int i = threadIdx.x; i < NN; i += 256) hsh[VV + i] = p[b*NN + i];
    __syncthreads();
    int wid = threadIdx.x >> 5, lane = threadIdx.x & 31;
    int v = blockIdx.x * 8 + wid;
    const float* Ur = U + (size_t)v*DD;
    float acc = 0.f;
    for (int j = lane; j < DD; j += 32) acc += hsh[j] * Ur[j];
    for (int o = 16; o; o >>= 1) acc += __shfl_down_sync(0xffffffffu, acc, o);
    if (lane == 0) out[b*VV + v] = acc;
}

// ---------------------------------------------------------------------------
extern "C" void kernel_launch(void* const* d_in, const int* in_sizes, int n_in,
                              void* d_out, int out_size) {
    const int*   tok = (const int*)  d_in[0];
    const float* R   = (const float*)d_in[1];
    const float* U   = (const float*)d_in[2];
    float*       out = (float*)d_out;

    bf16 *Rb, *S, *P, *T, *A, *PN;
    float *qp, *u, *sr, *a, *p, *c;
    cudaGetSymbolAddress((void**)&Rb, g_Rb);
    cudaGetSymbolAddress((void**)&S,  g_S);
    cudaGetSymbolAddress((void**)&P,  g_P);
    cudaGetSymbolAddress((void**)&T,  g_T);
    cudaGetSymbolAddress((void**)&A,  g_A);
    cudaGetSymbolAddress((void**)&PN, g_PN);
    cudaGetSymbolAddress((void**)&qp, g_qp);
    cudaGetSymbolAddress((void**)&u,  g_u);
    cudaGetSymbolAddress((void**)&sr, g_sr);
    cudaGetSymbolAddress((void**)&a,  g_a);
    cudaGetSymbolAddress((void**)&p,  g_p);
    cudaGetSymbolAddress((void**)&c,  g_c);

    const int SM0 = (3*ASTG_H + 3*BC<0>::STG) * 2;
    const int SM1 = (3*ASTG_H + 3*BC<1>::STG) * 2;
    cudaFuncSetAttribute(gemm_bf16<0>, cudaFuncAttributeMaxDynamicSharedMemorySize, SM0);
    cudaFuncSetAttribute(gemm_bf16<1>, cudaFuncAttributeMaxDynamicSharedMemorySize, SM1);
    cudaFuncSetAttribute(gemm_bf16<2>, cudaFuncAttributeMaxDynamicSharedMemorySize, SM0);

    dim3 gRow(NN, BB), gRow4(NN/4, BB), gT(8, 8, BB);
    const size_t RS = (size_t)DD*DD;

    // R layer 0 -> bf16, then layer-1 fused (rows + conv of R layers 1..3)
    r_conv0  <<<(DD*DD)/1024, 256>>>(R, Rb);
    gsm1_conv<<<dim3(256, 32 + 27), 256>>>(R, Rb, tok, P);

    // Layer 2: scores = P*S2*P^T ; A2 = softmax ; P3 = A2*P
    gather_S      <<<gRow4, 256>>>(Rb + 1*RS, tok, S);
    gemm_bf16<0>  <<<gT, 256, SM0>>>(P, S, T);
    gemm_bf16<1>  <<<gT, 256, SM1>>>(T, P, A);
    softmax_causal<<<gRow, 256>>>(A, A);
    gemm_bf16<2>  <<<gT, 256, SM0>>>(A, P, PN);

    // Layer 3: same with P3 (in PN) -> P4 (into P)
    gather_S      <<<gRow4, 256>>>(Rb + 2*RS, tok, S);
    gemm_bf16<0>  <<<gT, 256, SM0>>>(PN, S, T);
    gemm_bf16<1>  <<<gT, 256, SM1>>>(T, PN, A);
    softmax_causal<<<gRow, 256>>>(A, A);
    gemm_bf16<2>  <<<gT, 256, SM0>>>(A, PN, P);

    // Layer 4 (row 1023 only) + logits
    l4_q_part  <<<dim3(32, BB), 384>>>(Rb + 3*RS, tok, P, qp);
    l4_q_reduce<<<BB, 512>>>(qp, tok, u);
    l4_srow    <<<dim3(128, BB), 256>>>(u, P, sr);
    l4_softmax <<<BB, 256>>>(sr, a);
    l4_p       <<<dim3(4, BB), 256>>>(a, P, p);
    l4_c       <<<BB, 512>>>(tok, p, c);
    l4_logits  <<<dim3(64, BB), 256>>>(c, p, U, out);
}

// round 17
// speedup vs baseline: 1.1591x; 1.0392x over previous
#include <cuda_runtime.h>
#include <cuda_bf16.h>
#include <cstdint>

// Problem constants
#define BB 32
#define NN 1024
#define VV 512
#define DD 1536

typedef __nv_bfloat16 bf16;

// Scratch buffers (allocation-free rule: __device__ globals). Big tensors bf16.
__device__ bf16  g_Rb[(size_t)4*DD*DD];   // bf16 copy of R (all layers)
__device__ bf16  g_S [(size_t)BB*NN*NN];
__device__ bf16  g_P [(size_t)BB*NN*NN];
__device__ bf16  g_T [(size_t)BB*NN*NN];
__device__ bf16  g_A [(size_t)BB*NN*NN];
__device__ bf16  g_PN[(size_t)BB*NN*NN];
__device__ float g_ps [(size_t)BB*8*NN];  // per-(bj,row) exp partial sums
__device__ float g_inv[BB*NN];            // 1/rowsum
__device__ float g_qp[(size_t)BB*32*DD];
__device__ float g_u [BB*NN];
__device__ float g_sr[BB*NN];
__device__ float g_a [BB*NN];
__device__ float g_p [BB*NN];
__device__ float g_c [BB*VV];

__device__ __forceinline__ float2 bf2f(uint32_t u) {
    return __bfloat1622float2(*(__nv_bfloat162*)&u);
}

// Block-wide reductions over 8 warps (256 threads), value broadcast to all.
__device__ __forceinline__ float blk_max(float v, float* rs, int t) {
    #pragma unroll
    for (int o = 16; o; o >>= 1) v = fmaxf(v, __shfl_xor_sync(0xffffffffu, v, o));
    if ((t & 31) == 0) rs[t >> 5] = v;
    __syncthreads();
    float r = rs[0];
    #pragma unroll
    for (int w = 1; w < 8; w++) r = fmaxf(r, rs[w]);
    return r;
}
__device__ __forceinline__ float blk_sum(float v, float* rs, int t) {
    #pragma unroll
    for (int o = 16; o; o >>= 1) v += __shfl_xor_sync(0xffffffffu, v, o);
    if ((t & 31) == 0) rs[t >> 5] = v;
    __syncthreads();
    float r = rs[0];
    #pragma unroll
    for (int w = 1; w < 8; w++) r += rs[w];
    return r;
}

__device__ __forceinline__ void conv_chunk(const float* __restrict__ src,
                                           bf16* __restrict__ dst, size_t i) {
    float4 v = *(const float4*)(src + i);
    __nv_bfloat162 o0 = __floats2bfloat162_rn(v.x, v.y);
    __nv_bfloat162 o1 = __floats2bfloat162_rn(v.z, v.w);
    uint2 out; out.x = *(uint32_t*)&o0; out.y = *(uint32_t*)&o1;
    *(uint2*)(dst + i) = out;
}

// ---------------------------------------------------------------------------
// R layer-0 -> bf16 (small; runs before gsm1_conv)
// ---------------------------------------------------------------------------
__global__ void r_conv0(const float* __restrict__ R, bf16* __restrict__ Rb) {
    conv_chunk(R, Rb, ((size_t)blockIdx.x * 256 + threadIdx.x) * 4);
}

// ---------------------------------------------------------------------------
// Fused layer 1 (4 rows/block) + R layers 1-3 conversion merged in.
// ---------------------------------------------------------------------------
__global__ void __launch_bounds__(256)
gsm1_conv(const float* __restrict__ R, bf16* __restrict__ Rb,
          const int* __restrict__ tok, bf16* __restrict__ P) {
    int t = threadIdx.x;
    if (blockIdx.y >= 32) {                    // convert R layers 1..3
        size_t cidx = ((size_t)(blockIdx.y - 32) * 256 + blockIdx.x);
        size_t i = (size_t)DD*DD + cidx*1024 + t*4;
        conv_chunk(R, Rb, i);
        return;
    }
    int b = blockIdx.y;
    __shared__ float Wsh[DD];
    __shared__ int   tsh[NN];
    __shared__ float rs[8];
    const int* tb = tok + b*NN;
    for (int i = t; i < NN; i += 256) tsh[i] = tb[i];
    int i0 = t*4;
    #pragma unroll
    for (int r = 0; r < 4; r++) {
        int m = blockIdx.x*4 + r;
        __syncthreads();
        int tm = tb[m];
        const bf16* r0 = Rb + (size_t)tm*DD;
        const bf16* r1 = Rb + (size_t)(VV + m)*DD;
        for (int d4 = t*4; d4 < DD; d4 += 1024) {
            uint2 u0 = *(const uint2*)(r0 + d4);
            uint2 u1 = *(const uint2*)(r1 + d4);
            float2 a0 = bf2f(u0.x), a1 = bf2f(u0.y);
            float2 b0 = bf2f(u1.x), b1 = bf2f(u1.y);
            *(float4*)&Wsh[d4] = make_float4(a0.x+b0.x, a0.y+b0.y, a1.x+b1.x, a1.y+b1.y);
        }
        __syncthreads();
        float v[4];
        #pragma unroll
        for (int k = 0; k < 4; k++)
            v[k] = (i0+k <= m) ? (Wsh[tsh[i0+k]] + Wsh[VV + i0+k]) : -1e30f;
        float mx = blk_max(fmaxf(fmaxf(v[0], v[1]), fmaxf(v[2], v[3])), rs, t);
        __syncthreads();
        float e[4];
        #pragma unroll
        for (int k = 0; k < 4; k++)
            e[k] = (i0+k <= m) ? __expf(v[k] - mx) : 0.f;
        float sum = blk_sum(e[0]+e[1]+e[2]+e[3], rs, t);
        float inv = 1.f / sum;
        int kmax = ((m >> 7) + 1) << 7;
        if (i0 < kmax) {
            __nv_bfloat162 o0 = __floats2bfloat162_rn(e[0]*inv, e[1]*inv);
            __nv_bfloat162 o1 = __floats2bfloat162_rn(e[2]*inv, e[3]*inv);
            uint2 out; out.x = *(uint32_t*)&o0; out.y = *(uint32_t*)&o1;
            *(uint2*)(P + ((size_t)b*NN + m)*NN + i0) = out;
        }
    }
}

// ---------------------------------------------------------------------------
// S_k gather: 4 rows per block, 8B vector loads/stores.
// ---------------------------------------------------------------------------
__global__ void __launch_bounds__(256)
gather_S(const bf16* __restrict__ Rb, const int* __restrict__ tok,
         bf16* __restrict__ S) {
    int b = blockIdx.y;
    __shared__ float Wsh[DD];
    __shared__ int   tsh[NN];
    const int* tb = tok + b*NN;
    int t = threadIdx.x;
    for (int i = t; i < NN; i += 256) tsh[i] = tb[i];
    int i0 = t*4;
    #pragma unroll
    for (int r = 0; r < 4; r++) {
        int m = blockIdx.x*4 + r;
        __syncthreads();
        int tm = tb[m];
        const bf16* r0 = Rb + (size_t)tm*DD;
        const bf16* r1 = Rb + (size_t)(VV + m)*DD;
        for (int d4 = t*4; d4 < DD; d4 += 1024) {
            uint2 u0 = *(const uint2*)(r0 + d4);
            uint2 u1 = *(const uint2*)(r1 + d4);
            float2 a0 = bf2f(u0.x), a1 = bf2f(u0.y);
            float2 b0 = bf2f(u1.x), b1 = bf2f(u1.y);
            *(float4*)&Wsh[d4] = make_float4(a0.x+b0.x, a0.y+b0.y, a1.x+b1.x, a1.y+b1.y);
        }
        __syncthreads();
        float4 wp = *(const float4*)&Wsh[VV + i0];
        float v0 = Wsh[tsh[i0+0]] + wp.x;
        float v1 = Wsh[tsh[i0+1]] + wp.y;
        float v2 = Wsh[tsh[i0+2]] + wp.z;
        float v3 = Wsh[tsh[i0+3]] + wp.w;
        __nv_bfloat162 o0 = __floats2bfloat162_rn(v0, v1);
        __nv_bfloat162 o1 = __floats2bfloat162_rn(v2, v3);
        uint2 out; out.x = *(uint32_t*)&o0; out.y = *(uint32_t*)&o1;
        *(uint2*)(S + ((size_t)b*NN + m)*NN + i0) = out;
    }
}

// ---------------------------------------------------------------------------
// Row-sum inverse: inv[row] = 1 / sum_{bj<=row>>7} ps[bj][row]
// ---------------------------------------------------------------------------
__global__ void sum_inv(const float* __restrict__ ps, float* __restrict__ inv) {
    int b = blockIdx.x;
    for (int r = threadIdx.x; r < NN; r += 256) {
        float s = 0.f;
        int bimax = r >> 7;
        for (int bj = 0; bj <= bimax; bj++)
            s += ps[((size_t)b*8 + bj)*NN + r];
        inv[b*NN + r] = 1.f / s;
    }
}

// ---------------------------------------------------------------------------
// Batched bf16 GEMM: mma.sync m16n8k16, ldmatrix, 3-stage cp.async.
// ALL modes triangular (bj <= bi); bi reversed (heavy tiles first).
// MODE 0: C = A*B      k in [0,(bi+1)*128)
// MODE 1: C = exp(A*B^T) masked-causal, unnormalized; row partial sums -> ps.
//         (scores ~1e-3 so exp without max-shift is numerically safe)
// MODE 2: C = inv[row] * (A*B)   k in [bj*128,(bi+1)*128), zero strict-upper
// ---------------------------------------------------------------------------
#define ASTG_H (128*40)
template<int MODE>
struct BC { static constexpr int STR = 136, STG = 32*136; };
template<> struct BC<1> { static constexpr int STR = 40, STG = 128*40; };

template<int MODE>
__global__ void __launch_bounds__(256)
gemm_bf16(const bf16* __restrict__ Ag, const bf16* __restrict__ Bg,
          bf16* __restrict__ Cg, float* __restrict__ ps,
          const float* __restrict__ invv) {
    constexpr int BSTR = BC<MODE>::STR;
    constexpr int BSTG = BC<MODE>::STG;
    int bi = (int)gridDim.y - 1 - (int)blockIdx.y;   // heavy tiles first
    int bj = blockIdx.x, b = blockIdx.z;
    if (bj > bi) return;
    const bf16* Ab = Ag + (size_t)b*NN*NN;
    const bf16* Bb = Bg + (size_t)b*NN*NN;
    bf16*       Cb = Cg + (size_t)b*NN*NN;
    int k0 = (MODE == 2) ? bj*128 : 0;
    int k1 = (MODE == 1) ? (bj+1)*128 : (bi+1)*128;

    extern __shared__ __align__(16) bf16 sm[];
    uint32_t smbase = (uint32_t)__cvta_generic_to_shared(sm);
    uint32_t AB = smbase;
    uint32_t BBs = smbase + 3*ASTG_H*2;
    __shared__ float rowsum[128][2];

    int tid  = threadIdx.x;
    int wid  = tid >> 5, lane = tid & 31;
    int gid  = lane >> 2, tig = lane & 3;
    int g    = lane >> 3, rsel = lane & 7;
    int wm   = (wid & 3) * 32;
    int wn   = (wid >> 2) * 64;
    int row0 = bi*128, col0 = bj*128;

    float c[2][8][4] = {};

    auto load_stage = [&](int s, int kb) {
        uint32_t Ad = AB + (s*ASTG_H)*2;
        #pragma unroll
        for (int h = 0; h < 2; h++) {
            int chunk = tid + 256*h;
            int r = chunk >> 2, c8 = (chunk & 3) * 8;
            uint32_t dst = Ad + (r*40 + c8)*2;
            const bf16* src = &Ab[(size_t)(row0 + r)*NN + kb + c8];
            asm volatile("cp.async.ca.shared.global [%0], [%1], 16;\n" :: "r"(dst), "l"(src));
        }
        uint32_t Bd = BBs + (s*BSTG)*2;
        if (MODE == 1) {
            #pragma unroll
            for (int h = 0; h < 2; h++) {
                int chunk = tid + 256*h;
                int r = chunk >> 2, c8 = (chunk & 3) * 8;
                uint32_t dst = Bd + (r*BSTR + c8)*2;
                const bf16* src = &Bb[(size_t)(col0 + r)*NN + kb + c8];
                asm volatile("cp.async.ca.shared.global [%0], [%1], 16;\n" :: "r"(dst), "l"(src));
            }
        } else {
            #pragma unroll
            for (int h = 0; h < 2; h++) {
                int chunk = tid + 256*h;
                int r = chunk >> 4, c8 = (chunk & 15) * 8;
                uint32_t dst = Bd + (r*BSTR + c8)*2;
                const bf16* src = &Bb[(size_t)(kb + r)*NN + col0 + c8];
                asm volatile("cp.async.ca.shared.global [%0], [%1], 16;\n" :: "r"(dst), "l"(src));
            }
        }
    };

    auto compute = [&](int s) {
        uint32_t Ac = AB + (s*ASTG_H)*2;
        uint32_t Bc = BBs + (s*BSTG)*2;
        #pragma unroll
        for (int kk = 0; kk < 32; kk += 16) {
            uint32_t a[2][4];
            #pragma unroll
            for (int i = 0; i < 2; i++) {
                int row = wm + i*16 + (g & 1)*8 + rsel;
                int col = kk + (g >> 1)*8;
                uint32_t addr = Ac + (row*40 + col)*2;
                asm volatile("ldmatrix.sync.aligned.m8n8.x4.shared.b16 {%0,%1,%2,%3}, [%4];"
                             : "=r"(a[i][0]), "=r"(a[i][1]), "=r"(a[i][2]), "=r"(a[i][3])
                             : "r"(addr));
            }
            uint32_t bfr[8][2];
            #pragma unroll
            for (int u = 0; u < 4; u++) {
                int n0 = wn + u*16;
                uint32_t r0, r1, r2, r3;
                if (MODE == 1) {
                    int n = n0 + (g >> 1)*8 + rsel;
                    int k = kk + (g & 1)*8;
                    uint32_t addr = Bc + (n*BSTR + k)*2;
                    asm volatile("ldmatrix.sync.aligned.m8n8.x4.shared.b16 {%0,%1,%2,%3}, [%4];"
                                 : "=r"(r0), "=r"(r1), "=r"(r2), "=r"(r3) : "r"(addr));
                } else {
                    int k = kk + (g & 1)*8 + rsel;
                    int n = n0 + (g >> 1)*8;
                    uint32_t addr = Bc + (k*BSTR + n)*2;
                    asm volatile("ldmatrix.sync.aligned.m8n8.x4.trans.shared.b16 {%0,%1,%2,%3}, [%4];"
                                 : "=r"(r0), "=r"(r1), "=r"(r2), "=r"(r3) : "r"(addr));
                }
                bfr[2*u  ][0] = r0; bfr[2*u  ][1] = r1;
                bfr[2*u+1][0] = r2; bfr[2*u+1][1] = r3;
            }
            #pragma unroll
            for (int i = 0; i < 2; i++)
                #pragma unroll
                for (int j = 0; j < 8; j++) {
                    asm volatile(
                        "mma.sync.aligned.m16n8k16.row.col.f32.bf16.bf16.f32 "
                        "{%0,%1,%2,%3}, {%4,%5,%6,%7}, {%8,%9}, {%0,%1,%2,%3};"
                        : "+f"(c[i][j][0]), "+f"(c[i][j][1]),
                          "+f"(c[i][j][2]), "+f"(c[i][j][3])
                        : "r"(a[i][0]), "r"(a[i][1]), "r"(a[i][2]), "r"(a[i][3]),
                          "r"(bfr[j][0]), "r"(bfr[j][1]));
                }
        }
    };

    int nslab = (k1 - k0) >> 5;
    load_stage(0, k0);
    asm volatile("cp.async.commit_group;\n");
    load_stage(1, k0 + 32);
    asm volatile("cp.async.commit_group;\n");

    int sc = 0, sl = 2;
    for (int t = 0; t < nslab - 1; t++) {
        asm volatile("cp.async.wait_group 1;\n");
        __syncthreads();
        if (t + 2 < nslab) {
            load_stage(sl, k0 + (t+2)*32);
            asm volatile("cp.async.commit_group;\n");
            sl = (sl == 2) ? 0 : sl + 1;
        }
        compute(sc);
        sc = (sc == 2) ? 0 : sc + 1;
    }
    asm volatile("cp.async.wait_group 0;\n");
    __syncthreads();
    compute(sc);

    if (MODE == 1) {
        // exp epilogue: mask, exp, bf16-round, store; accumulate bf16-rounded
        // row sums (matches what gemm<2> will consume).
        float racc[2][2] = {};
        #pragma unroll
        for (int i = 0; i < 2; i++) {
            #pragma unroll
            for (int j = 0; j < 8; j++) {
                int gc = col0 + wn + j*8 + tig*2;
                #pragma unroll
                for (int h = 0; h < 2; h++) {
                    int gr = row0 + wm + i*16 + gid + h*8;
                    float ex = (gc+0 <= gr) ? __expf(c[i][j][h*2  ]) : 0.f;
                    float ey = (gc+1 <= gr) ? __expf(c[i][j][h*2+1]) : 0.f;
                    __nv_bfloat162 v = __floats2bfloat162_rn(ex, ey);
                    *(__nv_bfloat162*)&Cb[(size_t)gr*NN + gc] = v;
                    float2 rb = __bfloat1622float2(v);
                    racc[i][h] += rb.x + rb.y;
                }
            }
        }
        #pragma unroll
        for (int i = 0; i < 2; i++)
            #pragma unroll
            for (int h = 0; h < 2; h++) {
                float v = racc[i][h];
                v += __shfl_xor_sync(0xffffffffu, v, 1);
                v += __shfl_xor_sync(0xffffffffu, v, 2);
                if (tig == 0)
                    rowsum[wm + i*16 + gid + h*8][wid >> 2] = v;
            }
        __syncthreads();
        if (tid < 128)
            ps[((size_t)b*8 + bj)*NN + row0 + tid] = rowsum[tid][0] + rowsum[tid][1];
    } else {
        #pragma unroll
        for (int i = 0; i < 2; i++) {
            #pragma unroll
            for (int j = 0; j < 8; j++) {
                int gc = col0 + wn + j*8 + tig*2;
                #pragma unroll
                for (int h = 0; h < 2; h++) {
                    int gr = row0 + wm + i*16 + gid + h*8;
                    float vx = c[i][j][h*2], vy = c[i][j][h*2+1];
                    if (MODE == 2) {
                        float sc_ = invv[b*NN + gr];
                        vx *= sc_; vy *= sc_;
                        if (gc+0 > gr) vx = 0.f;
                        if (gc+1 > gr) vy = 0.f;
                    }
                    __nv_bfloat162 v = __floats2bfloat162_rn(vx, vy);
                    *(__nv_bfloat162*)&Cb[(size_t)gr*NN + gc] = v;
                }
            }
        }
    }
}

// ---------------------------------------------------------------------------
// Layer 4 (row 1023 only) + logits; causal-bounded reads of P4.
// ---------------------------------------------------------------------------
__global__ void __launch_bounds__(384)
l4_q_part(const bf16* __restrict__ Rb, const int* __restrict__ tok,
          const bf16* __restrict__ P, float* __restrict__ qp) {
    int b = blockIdx.y, bm = blockIdx.x;
    __shared__ float rsh[32];
    __shared__ int   tsh[32];
    int t = threadIdx.x;
    if (t < 32) {
        int m = bm*32 + t;
        rsh[t] = __bfloat162float(P[((size_t)b*NN + (NN-1))*NN + m]);
        tsh[t] = tok[b*NN + m];
    }
    __syncthreads();
    int d0 = t*4;
    float acc[4] = {};
    #pragma unroll 4
    for (int j = 0; j < 32; j++) {
        int m = bm*32 + j;
        float r = rsh[j];
        uint2 u0 = *(const uint2*)(Rb + (size_t)tsh[j]*DD + d0);
        uint2 u1 = *(const uint2*)(Rb + (size_t)(VV + m)*DD + d0);
        float2 a0 = bf2f(u0.x), a1 = bf2f(u0.y);
        float2 b0 = bf2f(u1.x), b1 = bf2f(u1.y);
        acc[0] += r * (a0.x + b0.x);
        acc[1] += r * (a0.y + b0.y);
        acc[2] += r * (a1.x + b1.x);
        acc[3] += r * (a1.y + b1.y);
    }
    *(float4*)&qp[((size_t)b*32 + bm)*DD + d0] = make_float4(acc[0], acc[1], acc[2], acc[3]);
}

__global__ void __launch_bounds__(512)
l4_q_reduce(const float* __restrict__ qp, const int* __restrict__ tok,
            float* __restrict__ u) {
    int b = blockIdx.x;
    __shared__ float qsh[DD];
    int t = threadIdx.x;
    for (int d = t; d < DD; d += 512) {
        float acc = 0.f;
        #pragma unroll 8
        for (int bm = 0; bm < 32; bm++)
            acc += qp[((size_t)b*32 + bm)*DD + d];
        qsh[d] = acc;
    }
    __syncthreads();
    for (int m = t; m < NN; m += 512)
        u[b*NN + m] = qsh[tok[b*NN + m]] + qsh[VV + m];
}

__global__ void l4_srow(const float* __restrict__ u, const bf16* __restrict__ P,
                        float* __restrict__ srow) {
    int b = blockIdx.y;
    __shared__ float ush[NN];
    for (int i = threadIdx.x; i < NN; i += 256) ush[i] = u[b*NN + i];
    __syncthreads();
    int row  = blockIdx.x * 8 + (threadIdx.x >> 5);
    int lane = threadIdx.x & 31;
    int kmax = ((row >> 7) + 1) << 7;        // causal bound
    const bf16* Prow = P + ((size_t)b*NN + row)*NN;
    float acc = 0.f;
    for (int kk = lane*2; kk < kmax; kk += 64) {
        float2 mv = bf2f(*(const uint32_t*)&Prow[kk]);
        acc += ush[kk]*mv.x + ush[kk+1]*mv.y;
    }
    for (int o = 16; o; o >>= 1) acc += __shfl_down_sync(0xffffffffu, acc, o);
    if (lane == 0) srow[b*NN + row] = acc;
}

__global__ void l4_softmax(const float* __restrict__ s, float* __restrict__ a) {
    int b = blockIdx.x;
    __shared__ float rs[8];
    int t = threadIdx.x;
    int i0 = t*4;
    float4 v4 = *(const float4*)&s[b*NN + i0];
    float v[4] = { v4.x, v4.y, v4.z, v4.w };
    float mx = blk_max(fmaxf(fmaxf(v[0], v[1]), fmaxf(v[2], v[3])), rs, t);
    __syncthreads();
    float e[4];
    #pragma unroll
    for (int k = 0; k < 4; k++) e[k] = __expf(v[k] - mx);
    float sum = blk_sum(e[0]+e[1]+e[2]+e[3], rs, t);
    float inv = 1.f / sum;
    *(float4*)&a[b*NN + i0] = make_float4(e[0]*inv, e[1]*inv, e[2]*inv, e[3]*inv);
}

__global__ void l4_p(const float* __restrict__ a, const bf16* __restrict__ P,
                     float* __restrict__ p) {
    int b = blockIdx.y;
    int k = blockIdx.x * 256 + threadIdx.x;
    __shared__ float ash[NN];
    for (int i = threadIdx.x; i < NN; i += 256) ash[i] = a[b*NN + i];
    __syncthreads();
    int m0 = k & ~127;                        // causal bound
    float acc = 0.f;
    for (int m = m0; m < NN; m++)
        acc += ash[m] * __bfloat162float(P[((size_t)b*NN + m)*NN + k]);
    p[b*NN + k] = acc;
}

__global__ void l4_c(const int* __restrict__ tok, const float* __restrict__ p,
                     float* __restrict__ c) {
    int b = blockIdx.x;
    __shared__ float psh[NN];
    __shared__ int   tsh[NN];
    for (int i = threadIdx.x; i < NN; i += blockDim.x) {
        psh[i] = p[b*NN + i];
        tsh[i] = tok[b*NN + i];
    }
    __syncthreads();
    int w = threadIdx.x;  // blockDim.x == 512 == VV
    float acc = 0.f;
    for (int m = 0; m < NN; m++)
        if (tsh[m] == w) acc += psh[m];
    c[b*VV + w] = acc;
}

__global__ void l4_logits(const float* __restrict__ c, const float* __restrict__ p,
                          const float* __restrict__ U, float* __restrict__ out) {
    int b = blockIdx.y;
    __shared__ float hsh[DD];
    for (int i = threadIdx.x; i < VV; i += 256) hsh[i]      = c[b*VV + i];
    for (int i = threadIdx.x; i < NN; i += 256) hsh[VV + i] = p[b*NN + i];
    __syncthreads();
    int wid = threadIdx.x >> 5, lane = threadIdx.x & 31;
    int v = blockIdx.x * 8 + wid;
    const float* Ur = U + (size_t)v*DD;
    float acc = 0.f;
    for (int j = lane; j < DD; j += 32) acc += hsh[j] * Ur[j];
    for (int o = 16; o; o >>= 1) acc += __shfl_down_sync(0xffffffffu, acc, o);
    if (lane == 0) out[b*VV + v] = acc;
}

// ---------------------------------------------------------------------------
extern "C" void kernel_launch(void* const* d_in, const int* in_sizes, int n_in,
                              void* d_out, int out_size) {
    const int*   tok = (const int*)  d_in[0];
    const float* R   = (const float*)d_in[1];
    const float* U   = (const float*)d_in[2];
    float*       out = (float*)d_out;

    bf16 *Rb, *S, *P, *T, *A, *PN;
    float *ps, *invv, *qp, *u, *sr, *a, *p, *c;
    cudaGetSymbolAddress((void**)&Rb,  g_Rb);
    cudaGetSymbolAddress((void**)&S,   g_S);
    cudaGetSymbolAddress((void**)&P,   g_P);
    cudaGetSymbolAddress((void**)&T,   g_T);
    cudaGetSymbolAddress((void**)&A,   g_A);
    cudaGetSymbolAddress((void**)&PN,  g_PN);
    cudaGetSymbolAddress((void**)&ps,  g_ps);
    cudaGetSymbolAddress((void**)&invv,g_inv);
    cudaGetSymbolAddress((void**)&qp,  g_qp);
    cudaGetSymbolAddress((void**)&u,   g_u);
    cudaGetSymbolAddress((void**)&sr,  g_sr);
    cudaGetSymbolAddress((void**)&a,   g_a);
    cudaGetSymbolAddress((void**)&p,   g_p);
    cudaGetSymbolAddress((void**)&c,   g_c);

    const int SM0 = (3*ASTG_H + 3*BC<0>::STG) * 2;
    const int SM1 = (3*ASTG_H + 3*BC<1>::STG) * 2;
    cudaFuncSetAttribute(gemm_bf16<0>, cudaFuncAttributeMaxDynamicSharedMemorySize, SM0);
    cudaFuncSetAttribute(gemm_bf16<1>, cudaFuncAttributeMaxDynamicSharedMemorySize, SM1);
    cudaFuncSetAttribute(gemm_bf16<2>, cudaFuncAttributeMaxDynamicSharedMemorySize, SM0);

    dim3 gRow4(NN/4, BB), gT(8, 8, BB);
    const size_t RS = (size_t)DD*DD;

    // R layer 0 -> bf16, then layer-1 fused (rows + conv of R layers 1..3)
    r_conv0  <<<(DD*DD)/1024, 256>>>(R, Rb);
    gsm1_conv<<<dim3(256, 32 + 27), 256>>>(R, Rb, tok, P);

    // Layer 2: E = exp(P*S2*P^T) [unnorm] ; P3 = inv * (E*P)
    gather_S    <<<gRow4, 256>>>(Rb + 1*RS, tok, S);
    gemm_bf16<0><<<gT, 256, SM0>>>(P, S, T, nullptr, nullptr);
    gemm_bf16<1><<<gT, 256, SM1>>>(T, P, A, ps, nullptr);
    sum_inv     <<<BB, 256>>>(ps, invv);
    gemm_bf16<2><<<gT, 256, SM0>>>(A, P, PN, nullptr, invv);

    // Layer 3: same with P3 (in PN) -> P4 (into P)
    gather_S    <<<gRow4, 256>>>(Rb + 2*RS, tok, S);
    gemm_bf16<0><<<gT, 256, SM0>>>(PN, S, T, nullptr, nullptr);
    gemm_bf16<1><<<gT, 256, SM1>>>(T, PN, A, ps, nullptr);
    sum_inv     <<<BB, 256>>>(ps, invv);
    gemm_bf16<2><<<gT, 256, SM0>>>(A, PN, P, nullptr, invv);

    // Layer 4 (row 1023 only) + logits
    l4_q_part  <<<dim3(32, BB), 384>>>(Rb + 3*RS, tok, P, qp);
    l4_q_reduce<<<BB, 512>>>(qp, tok, u);
    l4_srow    <<<dim3(128, BB), 256>>>(u, P, sr);
    l4_softmax <<<BB, 256>>>(sr, a);
    l4_p       <<<dim3(4, BB), 256>>>(a, P, p);
    l4_c       <<<BB, 512>>>(tok, p, c);
    l4_logits  <<<dim3(64, BB), 256>>>(c, p, U, out);
}